// round 9
// baseline (speedup 1.0000x reference)
#include <cuda_runtime.h>
#include <cstdint>
#include <math.h>

typedef unsigned int u32;

// Problem constants
#define B_  16
#define N_  1024
#define C_  256
#define NH_ 8
#define DH_ 32
#define M_  (B_*N_)      // 16384 rows
#define HID_ 1024

// ---------------------------------------------------------------------------
// Scratch (static __device__ arrays; no allocations allowed)
// ---------------------------------------------------------------------------
__device__ float g_y  [M_*C_];
__device__ float g_qkv[M_*3*C_];
__device__ float g_tmp[M_*C_];
__device__ float g_x2 [M_*C_];
__device__ float g_off[M_*64];
__device__ float g_awl[M_*32];
__device__ float g_vp [M_*C_];
__device__ float g_h1 [M_*HID_];

// ---------------------------------------------------------------------------
// tf32 helpers
// ---------------------------------------------------------------------------
__device__ __forceinline__ float tf32r(float x) {
    u32 u;
    asm("cvt.rna.tf32.f32 %0, %1;" : "=r"(u) : "f"(x));
    return __uint_as_float(u);
}

__device__ __forceinline__ void mma_tf32(float (&d)[4],
                                         const u32 (&a)[4],
                                         const u32 (&b)[2]) {
    asm volatile(
        "mma.sync.aligned.m16n8k8.row.col.f32.tf32.tf32.f32 "
        "{%0,%1,%2,%3}, {%4,%5,%6,%7}, {%8,%9}, {%0,%1,%2,%3};"
        : "+f"(d[0]), "+f"(d[1]), "+f"(d[2]), "+f"(d[3])
        : "r"(a[0]), "r"(a[1]), "r"(a[2]), "r"(a[3]),
          "r"(b[0]), "r"(b[1]));
}

__device__ __forceinline__ u32 smem_u32(const void* p) {
    return (u32)__cvta_generic_to_shared(p);
}

// ---------------------------------------------------------------------------
// LayerNorm: one block per row, 256 threads (C=256).
// Output is tf32-rounded (it is consumed only as a GEMM A-operand).
// ---------------------------------------------------------------------------
__global__ __launch_bounds__(256) void ln_kernel(
    const float* __restrict__ in, const float* __restrict__ w,
    const float* __restrict__ b, float* __restrict__ out)
{
    __shared__ float red[8];
    int row = blockIdx.x;
    int t = threadIdx.x;
    float v = in[(size_t)row*C_ + t];
    float s = v;
    #pragma unroll
    for (int o = 16; o; o >>= 1) s += __shfl_xor_sync(0xffffffffu, s, o);
    if ((t & 31) == 0) red[t >> 5] = s;
    __syncthreads();
    float tot = 0.f;
    #pragma unroll
    for (int i = 0; i < 8; i++) tot += red[i];
    float mean = tot * (1.0f/256.0f);
    __syncthreads();
    float d = v - mean;
    s = d*d;
    #pragma unroll
    for (int o = 16; o; o >>= 1) s += __shfl_xor_sync(0xffffffffu, s, o);
    if ((t & 31) == 0) red[t >> 5] = s;
    __syncthreads();
    tot = 0.f;
    #pragma unroll
    for (int i = 0; i < 8; i++) tot += red[i];
    float rs = rsqrtf(tot*(1.0f/256.0f) + 1e-5f);
    out[(size_t)row*C_ + t] = tf32r(d*rs*w[t] + b[t]);
}

// ---------------------------------------------------------------------------
// tf32 tensor-core GEMM, cp.async 2-stage double-buffered pipeline.
// Y[M,Nout] = X[M,K] @ W[Nout,K]^T (+bias)(+gelu)(+res)(+round)
// Block 128x128, BK=32, 8 warps in 2x4; warp tile 64x32.
// Operands land in smem as raw f32; the tf32 MMA truncates low bits (X is
// pre-rounded by its producer where it matters). Stride 36 = conflict-free.
// PAD: guards W rows/cols vs Nout. RND: tf32-round the output (fc1 -> fc2).
// ---------------------------------------------------------------------------
#define TSTR 36
#define GTILE (128*TSTR)              // floats per operand-stage
#define GSMEM (2*2*GTILE*4)           // 2 stages x (X,W) x 4B = 73728 B

template <int PAD, int RND>
__global__ __launch_bounds__(256) void gemm_tc_t(
    const float* __restrict__ X, const float* __restrict__ W,
    const float* __restrict__ bias, const float* __restrict__ res,
    float* __restrict__ Y, int M, int Nout, int K, int act)
{
    extern __shared__ float dsm[];
    int tid  = threadIdx.x;
    int warp = tid >> 5, lane = tid & 31;
    int g = lane >> 2, t = lane & 3;
    int wm0 = (warp >> 2) * 64;
    int wn0 = (warp & 3) * 32;
    int m0 = blockIdx.y * 128, n0 = blockIdx.x * 128;
    u32 sb = smem_u32(dsm);

    // issue one K-tile (stage s, k-offset k0) via cp.async
    auto issue_tile = [&](int s, int k0) {
        #pragma unroll
        for (int i = 0; i < 4; i++) {
            int idx = tid + (i << 8);
            int r  = idx >> 3;
            int c4 = (idx & 7) << 2;
            u32 dX = sb + (u32)((s*2*GTILE) + r*TSTR + c4)*4u;
            const float* gX = X + (size_t)(m0+r)*K + k0 + c4;
            asm volatile("cp.async.ca.shared.global [%0], [%1], 16;"
                         :: "r"(dX), "l"(gX));
            u32 dW = sb + (u32)((s*2*GTILE) + GTILE + r*TSTR + c4)*4u;
            const float* gW = W + (size_t)(n0+r)*K + k0 + c4;
            if (PAD) {
                int vld = (n0 + r < Nout) ? 16 : 0;
                asm volatile("cp.async.ca.shared.global [%0], [%1], 16, %2;"
                             :: "r"(dW), "l"(gW), "r"(vld));
            } else {
                asm volatile("cp.async.ca.shared.global [%0], [%1], 16;"
                             :: "r"(dW), "l"(gW));
            }
        }
    };

    float acc[4][4][4];
    #pragma unroll
    for (int mt = 0; mt < 4; mt++)
        #pragma unroll
        for (int nt = 0; nt < 4; nt++)
            #pragma unroll
            for (int c = 0; c < 4; c++) acc[mt][nt][c] = 0.f;

    issue_tile(0, 0);
    asm volatile("cp.async.commit_group;" ::: "memory");
    issue_tile(1, 32);
    asm volatile("cp.async.commit_group;" ::: "memory");

    int nk = K >> 5;
    for (int it = 0; it < nk; it++) {
        asm volatile("cp.async.wait_group 1;" ::: "memory");
        __syncthreads();

        const float* sX = dsm + (it & 1)*2*GTILE;
        const float* sW = sX + GTILE;
        #pragma unroll
        for (int ks = 0; ks < 4; ks++) {
            int kc = ks*8 + t;
            u32 a[4][4];
            #pragma unroll
            for (int mt = 0; mt < 4; mt++) {
                int r = wm0 + mt*16 + g;
                a[mt][0] = __float_as_uint(sX[r*TSTR     + kc]);
                a[mt][1] = __float_as_uint(sX[(r+8)*TSTR + kc]);
                a[mt][2] = __float_as_uint(sX[r*TSTR     + kc + 4]);
                a[mt][3] = __float_as_uint(sX[(r+8)*TSTR + kc + 4]);
            }
            u32 bb[4][2];
            #pragma unroll
            for (int nt = 0; nt < 4; nt++) {
                int r = wn0 + nt*8 + g;
                bb[nt][0] = __float_as_uint(sW[r*TSTR + kc]);
                bb[nt][1] = __float_as_uint(sW[r*TSTR + kc + 4]);
            }
            #pragma unroll
            for (int mt = 0; mt < 4; mt++)
                #pragma unroll
                for (int nt = 0; nt < 4; nt++)
                    mma_tf32(acc[mt][nt], a[mt], bb[nt]);
        }
        __syncthreads();

        int k2 = (it + 2) << 5;
        if (k2 < K) issue_tile(it & 1, k2);
        asm volatile("cp.async.commit_group;" ::: "memory");
    }

    #pragma unroll
    for (int mt = 0; mt < 4; mt++) {
        #pragma unroll
        for (int nt = 0; nt < 4; nt++) {
            int n = n0 + wn0 + nt*8 + 2*t;
            if (PAD && n >= Nout) continue;
            #pragma unroll
            for (int half = 0; half < 2; half++) {
                int m = m0 + wm0 + mt*16 + g + half*8;
                float v0 = acc[mt][nt][half*2 + 0];
                float v1 = acc[mt][nt][half*2 + 1];
                if (bias) { v0 += bias[n]; v1 += bias[n+1]; }
                if (act)  { v0 *= normcdff(v0); v1 *= normcdff(v1); }
                if (res)  { v0 += res[(size_t)m*Nout + n];
                            v1 += res[(size_t)m*Nout + n + 1]; }
                if (RND)  { v0 = tf32r(v0); v1 = tf32r(v1); }
                *(float2*)(Y + (size_t)m*Nout + n) = make_float2(v0, v1);
            }
        }
    }
}

// ---------------------------------------------------------------------------
// Flash attention v2 (tf32 mma, online softmax in registers).
// Block = (b, h, 128-query tile), 8 warps; warp owns 16 query rows.
// 64-key chunks, K/V register-prefetched one chunk ahead.
// Output tf32-rounded (feeds proj GEMM only).
// ---------------------------------------------------------------------------
#define FQT  128
#define FKC  64
#define QSTR 36
#define VSTR 68
#define FSMEM ((FQT*QSTR + FKC*QSTR + 32*VSTR)*4)

__global__ __launch_bounds__(256) void flash_tc(
    const float* __restrict__ qkv, float* __restrict__ out)
{
    extern __shared__ float sm[];
    float* q_s = sm;                    // FQT x 36
    float* k_s = sm + FQT*QSTR;         // FKC x 36
    float* v_s = k_s + FKC*QSTR;        // 32 x 68 (transposed: [dh][key])

    int tid  = threadIdx.x;
    int warp = tid >> 5, lane = tid & 31;
    int g = lane >> 2, t = lane & 3;
    int b = blockIdx.z, h = blockIdx.y;
    int q0 = blockIdx.x * FQT;
    const float* qb = qkv + (size_t)b*N_*768 + h*32;
    const float scale = 0.17677669529663687f;   // 32^-0.5 (folded into Q)

    for (int ii = tid; ii < FQT*8; ii += 256) {
        int r = ii >> 3, c4q = (ii & 7) << 2;
        float4 v = *(const float4*)(qb + (size_t)(q0+r)*768 + c4q);
        q_s[r*QSTR + c4q + 0] = tf32r(v.x*scale);
        q_s[r*QSTR + c4q + 1] = tf32r(v.y*scale);
        q_s[r*QSTR + c4q + 2] = tf32r(v.z*scale);
        q_s[r*QSTR + c4q + 3] = tf32r(v.w*scale);
    }

    int row0 = warp * 16;
    float oa[4][4];
    #pragma unroll
    for (int nt = 0; nt < 4; nt++)
        #pragma unroll
        for (int c = 0; c < 4; c++) oa[nt][c] = 0.f;
    float mr0 = -1e30f, mr1 = -1e30f, lr0 = 0.f, lr1 = 0.f;

    int src_lo = (lane & ~3) | (t >> 1);
    int src_hi = src_lo | 2;

    int rA = tid >> 3, rB = rA + 32;
    int c4 = (tid & 7) << 2;

    float4 kfA = *(const float4*)(qb + (size_t)rA*768 + 256 + c4);
    float4 kfB = *(const float4*)(qb + (size_t)rB*768 + 256 + c4);
    float4 vfA = *(const float4*)(qb + (size_t)rA*768 + 512 + c4);
    float4 vfB = *(const float4*)(qb + (size_t)rB*768 + 512 + c4);

    for (int kt = 0; kt < N_; kt += FKC) {
        __syncthreads();
        k_s[rA*QSTR + c4 + 0] = tf32r(kfA.x);
        k_s[rA*QSTR + c4 + 1] = tf32r(kfA.y);
        k_s[rA*QSTR + c4 + 2] = tf32r(kfA.z);
        k_s[rA*QSTR + c4 + 3] = tf32r(kfA.w);
        k_s[rB*QSTR + c4 + 0] = tf32r(kfB.x);
        k_s[rB*QSTR + c4 + 1] = tf32r(kfB.y);
        k_s[rB*QSTR + c4 + 2] = tf32r(kfB.z);
        k_s[rB*QSTR + c4 + 3] = tf32r(kfB.w);
        v_s[(c4+0)*VSTR + rA] = tf32r(vfA.x);
        v_s[(c4+1)*VSTR + rA] = tf32r(vfA.y);
        v_s[(c4+2)*VSTR + rA] = tf32r(vfA.z);
        v_s[(c4+3)*VSTR + rA] = tf32r(vfA.w);
        v_s[(c4+0)*VSTR + rB] = tf32r(vfB.x);
        v_s[(c4+1)*VSTR + rB] = tf32r(vfB.y);
        v_s[(c4+2)*VSTR + rB] = tf32r(vfB.z);
        v_s[(c4+3)*VSTR + rB] = tf32r(vfB.w);
        __syncthreads();

        int ktn = kt + FKC;
        if (ktn < N_) {
            kfA = *(const float4*)(qb + (size_t)(ktn+rA)*768 + 256 + c4);
            kfB = *(const float4*)(qb + (size_t)(ktn+rB)*768 + 256 + c4);
            vfA = *(const float4*)(qb + (size_t)(ktn+rA)*768 + 512 + c4);
            vfB = *(const float4*)(qb + (size_t)(ktn+rB)*768 + 512 + c4);
        }

        float s[8][4];
        #pragma unroll
        for (int nt = 0; nt < 8; nt++)
            #pragma unroll
            for (int c = 0; c < 4; c++) s[nt][c] = 0.f;

        #pragma unroll
        for (int ks = 0; ks < 4; ks++) {
            int kc = ks*8 + t;
            u32 a[4];
            a[0] = __float_as_uint(q_s[(row0+g)*QSTR   + kc]);
            a[1] = __float_as_uint(q_s[(row0+8+g)*QSTR + kc]);
            a[2] = __float_as_uint(q_s[(row0+g)*QSTR   + kc + 4]);
            a[3] = __float_as_uint(q_s[(row0+8+g)*QSTR + kc + 4]);
            u32 bb[8][2];
            #pragma unroll
            for (int nt = 0; nt < 8; nt++) {
                int rr = nt*8 + g;
                bb[nt][0] = __float_as_uint(k_s[rr*QSTR + kc]);
                bb[nt][1] = __float_as_uint(k_s[rr*QSTR + kc + 4]);
            }
            #pragma unroll
            for (int nt = 0; nt < 8; nt++)
                mma_tf32(s[nt], a, bb[nt]);
        }

        {
            float m0 = -1e30f, m1 = -1e30f;
            #pragma unroll
            for (int nt = 0; nt < 8; nt++) {
                m0 = fmaxf(m0, fmaxf(s[nt][0], s[nt][1]));
                m1 = fmaxf(m1, fmaxf(s[nt][2], s[nt][3]));
            }
            #pragma unroll
            for (int o = 1; o <= 2; o <<= 1) {
                m0 = fmaxf(m0, __shfl_xor_sync(0xffffffffu, m0, o));
                m1 = fmaxf(m1, __shfl_xor_sync(0xffffffffu, m1, o));
            }
            float mn0 = fmaxf(mr0, m0);
            float mn1 = fmaxf(mr1, m1);
            float sf0 = __expf(mr0 - mn0);
            float sf1 = __expf(mr1 - mn1);
            mr0 = mn0; mr1 = mn1;
            float ls0 = 0.f, ls1 = 0.f;
            #pragma unroll
            for (int nt = 0; nt < 8; nt++) {
                float e0 = __expf(s[nt][0] - mn0);
                float e1 = __expf(s[nt][1] - mn0);
                float e2 = __expf(s[nt][2] - mn1);
                float e3 = __expf(s[nt][3] - mn1);
                ls0 += e0 + e1;  ls1 += e2 + e3;
                s[nt][0] = tf32r(e0);  s[nt][1] = tf32r(e1);
                s[nt][2] = tf32r(e2);  s[nt][3] = tf32r(e3);
            }
            #pragma unroll
            for (int o = 1; o <= 2; o <<= 1) {
                ls0 += __shfl_xor_sync(0xffffffffu, ls0, o);
                ls1 += __shfl_xor_sync(0xffffffffu, ls1, o);
            }
            lr0 = lr0*sf0 + ls0;
            lr1 = lr1*sf1 + ls1;
            #pragma unroll
            for (int nt = 0; nt < 4; nt++) {
                oa[nt][0] *= sf0;  oa[nt][1] *= sf0;
                oa[nt][2] *= sf1;  oa[nt][3] *= sf1;
            }
        }

        #pragma unroll
        for (int k8 = 0; k8 < 8; k8++) {
            float y00 = __shfl_sync(0xffffffffu, s[k8][0], src_lo);
            float y01 = __shfl_sync(0xffffffffu, s[k8][1], src_lo);
            float y10 = __shfl_sync(0xffffffffu, s[k8][0], src_hi);
            float y11 = __shfl_sync(0xffffffffu, s[k8][1], src_hi);
            float z00 = __shfl_sync(0xffffffffu, s[k8][2], src_lo);
            float z01 = __shfl_sync(0xffffffffu, s[k8][3], src_lo);
            float z10 = __shfl_sync(0xffffffffu, s[k8][2], src_hi);
            float z11 = __shfl_sync(0xffffffffu, s[k8][3], src_hi);
            u32 a[4];
            a[0] = __float_as_uint((t & 1) ? y01 : y00);
            a[2] = __float_as_uint((t & 1) ? y11 : y10);
            a[1] = __float_as_uint((t & 1) ? z01 : z00);
            a[3] = __float_as_uint((t & 1) ? z11 : z10);
            u32 bb[4][2];
            #pragma unroll
            for (int nt = 0; nt < 4; nt++) {
                int d = nt*8 + g;
                bb[nt][0] = __float_as_uint(v_s[d*VSTR + k8*8 + t]);
                bb[nt][1] = __float_as_uint(v_s[d*VSTR + k8*8 + t + 4]);
            }
            #pragma unroll
            for (int nt = 0; nt < 4; nt++)
                mma_tf32(oa[nt], a, bb[nt]);
        }
    }

    float i0 = 1.f / lr0;
    float i1 = 1.f / lr1;
    int r = q0 + row0 + g;
    #pragma unroll
    for (int nt = 0; nt < 4; nt++) {
        int col = h*32 + nt*8 + 2*t;
        *(float2*)(out + ((size_t)b*N_ + r)*C_ + col) =
            make_float2(tf32r(oa[nt][0]*i0), tf32r(oa[nt][1]*i0));
        *(float2*)(out + ((size_t)b*N_ + r + 8)*C_ + col) =
            make_float2(tf32r(oa[nt][2]*i1), tf32r(oa[nt][3]*i1));
    }
}

// ---------------------------------------------------------------------------
// Deformable gather: one warp per (b, n, head); lane = channel d.
// Output tf32-rounded (feeds oproj GEMM only).
// ---------------------------------------------------------------------------
__global__ __launch_bounds__(128) void deform_kernel(
    const float* __restrict__ ref, const float* __restrict__ off,
    const float* __restrict__ awl, const float* __restrict__ vp,
    float* __restrict__ out)
{
    int u = (blockIdx.x << 2) + (threadIdx.x >> 5);
    int lane = threadIdx.x & 31;
    int h  = u & 7;
    int bn = u >> 3;
    int b  = bn >> 10;

    float rx = ref[(size_t)bn*2 + 0]*32.f - 0.5f;
    float ry = ref[(size_t)bn*2 + 1]*32.f - 0.5f;
    const float* offp = off + (size_t)bn*64 + h*8;
    const float* awp  = awl + (size_t)bn*32 + h*4;

    float a0 = awp[0], a1 = awp[1], a2 = awp[2], a3 = awp[3];
    float mx = fmaxf(fmaxf(a0,a1), fmaxf(a2,a3));
    float e0 = __expf(a0-mx), e1 = __expf(a1-mx), e2 = __expf(a2-mx), e3 = __expf(a3-mx);
    float inv = 1.f/(e0+e1+e2+e3);
    float aw4[4] = {e0*inv, e1*inv, e2*inv, e3*inv};

    const float* vb = vp + (size_t)b*N_*C_ + h*32 + lane;
    float acc = 0.f;
    #pragma unroll
    for (int p = 0; p < 4; p++) {
        float gx = rx + offp[p*2+0];
        float gy = ry + offp[p*2+1];
        float x0f = floorf(gx), y0f = floorf(gy);
        float lx = gx - x0f, ly = gy - y0f;
        int x0 = (int)x0f, y0 = (int)y0f;
        float s = 0.f;
        #pragma unroll
        for (int cy = 0; cy < 2; cy++) {
            int yi = y0 + cy;
            float wy = cy ? ly : (1.f - ly);
            bool vy = (yi >= 0) && (yi < 32);
            int yc = min(max(yi, 0), 31);
            #pragma unroll
            for (int cx = 0; cx < 2; cx++) {
                int xi = x0 + cx;
                float wx = cx ? lx : (1.f - lx);
                bool vx = (xi >= 0) && (xi < 32);
                int xc = min(max(xi, 0), 31);
                float val = (vx && vy) ? vb[(size_t)(yc*32 + xc)*C_] : 0.f;
                s = fmaf(val, wx*wy, s);
            }
        }
        acc = fmaf(aw4[p], s, acc);
    }
    out[(size_t)bn*C_ + h*32 + lane] = tf32r(acc);
}

// ---------------------------------------------------------------------------
// Launch
// ---------------------------------------------------------------------------
extern "C" void kernel_launch(void* const* d_in, const int* in_sizes, int n_in,
                              void* d_out, int out_size)
{
    const float* x       = (const float*)d_in[0];
    const float* ref     = (const float*)d_in[1];
    const float* value   = (const float*)d_in[2];
    const float* ln1w    = (const float*)d_in[3];
    const float* ln1b    = (const float*)d_in[4];
    const float* ln2w    = (const float*)d_in[5];
    const float* ln2b    = (const float*)d_in[6];
    const float* ln3w    = (const float*)d_in[7];
    const float* ln3b    = (const float*)d_in[8];
    const float* qkv_w   = (const float*)d_in[9];
    const float* proj_w  = (const float*)d_in[10];
    const float* proj_b  = (const float*)d_in[11];
    const float* off_w   = (const float*)d_in[12];
    const float* off_b   = (const float*)d_in[13];
    const float* aw_w    = (const float*)d_in[14];
    const float* aw_b    = (const float*)d_in[15];
    const float* vproj_w = (const float*)d_in[16];
    const float* vproj_b = (const float*)d_in[17];
    const float* oproj_w = (const float*)d_in[18];
    const float* oproj_b = (const float*)d_in[19];
    const float* fc1_w   = (const float*)d_in[20];
    const float* fc1_b   = (const float*)d_in[21];
    const float* fc2_w   = (const float*)d_in[22];
    const float* fc2_b   = (const float*)d_in[23];
    float* out = (float*)d_out;

    float *y, *qkvb, *tmp, *x2, *offb, *awb, *vpb, *h1;
    cudaGetSymbolAddress((void**)&y,    g_y);
    cudaGetSymbolAddress((void**)&qkvb, g_qkv);
    cudaGetSymbolAddress((void**)&tmp,  g_tmp);
    cudaGetSymbolAddress((void**)&x2,   g_x2);
    cudaGetSymbolAddress((void**)&offb, g_off);
    cudaGetSymbolAddress((void**)&awb,  g_awl);
    cudaGetSymbolAddress((void**)&vpb,  g_vp);
    cudaGetSymbolAddress((void**)&h1,   g_h1);

    cudaFuncSetAttribute(flash_tc,
        cudaFuncAttributeMaxDynamicSharedMemorySize, FSMEM);
    cudaFuncSetAttribute(gemm_tc_t<0,0>,
        cudaFuncAttributeMaxDynamicSharedMemorySize, GSMEM);
    cudaFuncSetAttribute(gemm_tc_t<1,0>,
        cudaFuncAttributeMaxDynamicSharedMemorySize, GSMEM);
    cudaFuncSetAttribute(gemm_tc_t<0,1>,
        cudaFuncAttributeMaxDynamicSharedMemorySize, GSMEM);

    // x1 = x + attn(ln1(x))
    ln_kernel<<<M_, 256>>>(x, ln1w, ln1b, y);
    gemm_tc_t<0,0><<<dim3(6,128), 256, GSMEM>>>(y, qkv_w, nullptr, nullptr, qkvb, M_, 768, 256, 0);
    flash_tc<<<dim3(N_/FQT, NH_, B_), 256, FSMEM>>>(qkvb, tmp);
    gemm_tc_t<0,0><<<dim3(2,128), 256, GSMEM>>>(tmp, proj_w, proj_b, x, x2, M_, 256, 256, 0);

    // x2 = x1 + deform(ln2(x1))
    ln_kernel<<<M_, 256>>>(x2, ln2w, ln2b, y);
    gemm_tc_t<1,0><<<dim3(1,128), 256, GSMEM>>>(y, off_w, off_b, nullptr, offb, M_, 64, 256, 0);
    gemm_tc_t<1,0><<<dim3(1,128), 256, GSMEM>>>(y, aw_w,  aw_b,  nullptr, awb,  M_, 32, 256, 0);
    gemm_tc_t<0,0><<<dim3(2,128), 256, GSMEM>>>(value, vproj_w, vproj_b, nullptr, vpb, M_, 256, 256, 0);
    deform_kernel<<<32768, 128>>>(ref, offb, awb, vpb, tmp);
    gemm_tc_t<0,0><<<dim3(2,128), 256, GSMEM>>>(tmp, oproj_w, oproj_b, x2, x2, M_, 256, 256, 0);

    // out = x2 + fc2(gelu(fc1(ln3(x2))))
    ln_kernel<<<M_, 256>>>(x2, ln3w, ln3b, y);
    gemm_tc_t<0,1><<<dim3(8,128), 256, GSMEM>>>(y, fc1_w, fc1_b, nullptr, h1, M_, 1024, 256, 1);
    gemm_tc_t<0,0><<<dim3(2,128), 256, GSMEM>>>(h1, fc2_w, fc2_b, x2, out, M_, 256, 1024, 0);
}

// round 10
// speedup vs baseline: 1.0405x; 1.0405x over previous
#include <cuda_runtime.h>
#include <cstdint>
#include <math.h>

typedef unsigned int u32;

// Problem constants
#define B_  16
#define N_  1024
#define C_  256
#define NH_ 8
#define DH_ 32
#define M_  (B_*N_)      // 16384 rows
#define HID_ 1024

// Weight segment sizes (floats)
#define WSZ_QKV   (3*C_*C_)     // 196608
#define WSZ_PROJ  (C_*C_)       // 65536
#define WSZ_OFF   (64*C_)       // 16384
#define WSZ_AW    (32*C_)       // 8192
#define WSZ_VPROJ (C_*C_)
#define WSZ_OPROJ (C_*C_)
#define WSZ_FC1   (HID_*C_)     // 262144
#define WSZ_FC2   (C_*HID_)     // 262144
#define WOFF_QKV   0
#define WOFF_PROJ  (WOFF_QKV  + WSZ_QKV)
#define WOFF_OFF   (WOFF_PROJ + WSZ_PROJ)
#define WOFF_AW    (WOFF_OFF  + WSZ_OFF)
#define WOFF_VPROJ (WOFF_AW   + WSZ_AW)
#define WOFF_OPROJ (WOFF_VPROJ+ WSZ_VPROJ)
#define WOFF_FC1   (WOFF_OPROJ+ WSZ_OPROJ)
#define WOFF_FC2   (WOFF_FC1  + WSZ_FC1)
#define WTOT       (WOFF_FC2  + WSZ_FC2)   // 942080

// ---------------------------------------------------------------------------
// Scratch (static __device__ arrays; no allocations allowed)
// ---------------------------------------------------------------------------
__device__ float g_y  [M_*C_];
__device__ float g_qkv[M_*3*C_];
__device__ float g_tmp[M_*C_];
__device__ float g_x2 [M_*C_];
__device__ float g_off[M_*64];
__device__ float g_awl[M_*32];
__device__ float g_vp [M_*C_];
__device__ float g_h1 [M_*HID_];
__device__ float g_w  [WTOT];      // tf32-rounded weights
__device__ float g_val[M_*C_];     // tf32-rounded value input

// ---------------------------------------------------------------------------
// tf32 helpers
// ---------------------------------------------------------------------------
__device__ __forceinline__ float tf32r(float x) {
    u32 u;
    asm("cvt.rna.tf32.f32 %0, %1;" : "=r"(u) : "f"(x));
    return __uint_as_float(u);
}

__device__ __forceinline__ void mma_tf32(float (&d)[4],
                                         const u32 (&a)[4],
                                         const u32 (&b)[2]) {
    asm volatile(
        "mma.sync.aligned.m16n8k8.row.col.f32.tf32.tf32.f32 "
        "{%0,%1,%2,%3}, {%4,%5,%6,%7}, {%8,%9}, {%0,%1,%2,%3};"
        : "+f"(d[0]), "+f"(d[1]), "+f"(d[2]), "+f"(d[3])
        : "r"(a[0]), "r"(a[1]), "r"(a[2]), "r"(a[3]),
          "r"(b[0]), "r"(b[1]));
}

__device__ __forceinline__ u32 smem_u32(const void* p) {
    return (u32)__cvta_generic_to_shared(p);
}

// ---------------------------------------------------------------------------
// Pre-round all weights into g_w (rna tf32), float4-granular.
// ---------------------------------------------------------------------------
__global__ __launch_bounds__(256) void round_weights(
    const float* __restrict__ qkv_w, const float* __restrict__ proj_w,
    const float* __restrict__ off_w, const float* __restrict__ aw_w,
    const float* __restrict__ vproj_w, const float* __restrict__ oproj_w,
    const float* __restrict__ fc1_w, const float* __restrict__ fc2_w,
    float* __restrict__ dst)
{
    int i4 = blockIdx.x*256 + threadIdx.x;     // float4 index
    if (i4 >= WTOT/4) return;
    int i = i4*4;
    const float* src;
    int off;
    if      (i < WOFF_PROJ)  { src = qkv_w;   off = i - WOFF_QKV;  }
    else if (i < WOFF_OFF)   { src = proj_w;  off = i - WOFF_PROJ; }
    else if (i < WOFF_AW)    { src = off_w;   off = i - WOFF_OFF;  }
    else if (i < WOFF_VPROJ) { src = aw_w;    off = i - WOFF_AW;   }
    else if (i < WOFF_OPROJ) { src = vproj_w; off = i - WOFF_VPROJ;}
    else if (i < WOFF_FC1)   { src = oproj_w; off = i - WOFF_OPROJ;}
    else if (i < WOFF_FC2)   { src = fc1_w;   off = i - WOFF_FC1;  }
    else                     { src = fc2_w;   off = i - WOFF_FC2;  }
    float4 v = *(const float4*)(src + off);
    v.x = tf32r(v.x); v.y = tf32r(v.y); v.z = tf32r(v.z); v.w = tf32r(v.w);
    *(float4*)(dst + i) = v;
}

__global__ __launch_bounds__(256) void round_buf(
    const float* __restrict__ src, float* __restrict__ dst, int n4)
{
    int i4 = blockIdx.x*256 + threadIdx.x;
    if (i4 >= n4) return;
    float4 v = *(const float4*)(src + i4*4);
    v.x = tf32r(v.x); v.y = tf32r(v.y); v.z = tf32r(v.z); v.w = tf32r(v.w);
    *(float4*)(dst + i4*4) = v;
}

// ---------------------------------------------------------------------------
// LayerNorm: one block per row, 256 threads (C=256). Output tf32-rounded.
// ---------------------------------------------------------------------------
__global__ __launch_bounds__(256) void ln_kernel(
    const float* __restrict__ in, const float* __restrict__ w,
    const float* __restrict__ b, float* __restrict__ out)
{
    __shared__ float red[8];
    int row = blockIdx.x;
    int t = threadIdx.x;
    float v = in[(size_t)row*C_ + t];
    float s = v;
    #pragma unroll
    for (int o = 16; o; o >>= 1) s += __shfl_xor_sync(0xffffffffu, s, o);
    if ((t & 31) == 0) red[t >> 5] = s;
    __syncthreads();
    float tot = 0.f;
    #pragma unroll
    for (int i = 0; i < 8; i++) tot += red[i];
    float mean = tot * (1.0f/256.0f);
    __syncthreads();
    float d = v - mean;
    s = d*d;
    #pragma unroll
    for (int o = 16; o; o >>= 1) s += __shfl_xor_sync(0xffffffffu, s, o);
    if ((t & 31) == 0) red[t >> 5] = s;
    __syncthreads();
    tot = 0.f;
    #pragma unroll
    for (int i = 0; i < 8; i++) tot += red[i];
    float rs = rsqrtf(tot*(1.0f/256.0f) + 1e-5f);
    out[(size_t)row*C_ + t] = tf32r(d*rs*w[t] + b[t]);
}

// ---------------------------------------------------------------------------
// tf32 tensor-core GEMM, cp.async 2-stage double-buffered pipeline.
// __launch_bounds__(256,2) forces regs<=128 so 2 CTAs/SM stay resident.
// All operands are pre-rounded (rna) by their producers.
// ---------------------------------------------------------------------------
#define TSTR 36
#define GTILE (128*TSTR)
#define GSMEM (2*2*GTILE*4)           // 73728 B

template <int PAD, int RND>
__global__ __launch_bounds__(256, 2) void gemm_tc_t(
    const float* __restrict__ X, const float* __restrict__ W,
    const float* __restrict__ bias, const float* __restrict__ res,
    float* __restrict__ Y, int M, int Nout, int K, int act)
{
    extern __shared__ float dsm[];
    int tid  = threadIdx.x;
    int warp = tid >> 5, lane = tid & 31;
    int g = lane >> 2, t = lane & 3;
    int wm0 = (warp >> 2) * 64;
    int wn0 = (warp & 3) * 32;
    int m0 = blockIdx.y * 128, n0 = blockIdx.x * 128;
    u32 sb = smem_u32(dsm);

    auto issue_tile = [&](int s, int k0) {
        #pragma unroll
        for (int i = 0; i < 4; i++) {
            int idx = tid + (i << 8);
            int r  = idx >> 3;
            int c4 = (idx & 7) << 2;
            u32 dX = sb + (u32)((s*2*GTILE) + r*TSTR + c4)*4u;
            const float* gX = X + (size_t)(m0+r)*K + k0 + c4;
            asm volatile("cp.async.ca.shared.global [%0], [%1], 16;"
                         :: "r"(dX), "l"(gX));
            u32 dW = sb + (u32)((s*2*GTILE) + GTILE + r*TSTR + c4)*4u;
            const float* gW = W + (size_t)(n0+r)*K + k0 + c4;
            if (PAD) {
                int vld = (n0 + r < Nout) ? 16 : 0;
                asm volatile("cp.async.ca.shared.global [%0], [%1], 16, %2;"
                             :: "r"(dW), "l"(gW), "r"(vld));
            } else {
                asm volatile("cp.async.ca.shared.global [%0], [%1], 16;"
                             :: "r"(dW), "l"(gW));
            }
        }
    };

    float acc[4][4][4];
    #pragma unroll
    for (int mt = 0; mt < 4; mt++)
        #pragma unroll
        for (int nt = 0; nt < 4; nt++)
            #pragma unroll
            for (int c = 0; c < 4; c++) acc[mt][nt][c] = 0.f;

    issue_tile(0, 0);
    asm volatile("cp.async.commit_group;" ::: "memory");
    issue_tile(1, 32);
    asm volatile("cp.async.commit_group;" ::: "memory");

    int nk = K >> 5;
    for (int it = 0; it < nk; it++) {
        asm volatile("cp.async.wait_group 1;" ::: "memory");
        __syncthreads();

        const float* sX = dsm + (it & 1)*2*GTILE;
        const float* sW = sX + GTILE;
        #pragma unroll
        for (int ks = 0; ks < 4; ks++) {
            int kc = ks*8 + t;
            u32 a[4][4];
            #pragma unroll
            for (int mt = 0; mt < 4; mt++) {
                int r = wm0 + mt*16 + g;
                a[mt][0] = __float_as_uint(sX[r*TSTR     + kc]);
                a[mt][1] = __float_as_uint(sX[(r+8)*TSTR + kc]);
                a[mt][2] = __float_as_uint(sX[r*TSTR     + kc + 4]);
                a[mt][3] = __float_as_uint(sX[(r+8)*TSTR + kc + 4]);
            }
            u32 bb[4][2];
            #pragma unroll
            for (int nt = 0; nt < 4; nt++) {
                int r = wn0 + nt*8 + g;
                bb[nt][0] = __float_as_uint(sW[r*TSTR + kc]);
                bb[nt][1] = __float_as_uint(sW[r*TSTR + kc + 4]);
            }
            #pragma unroll
            for (int mt = 0; mt < 4; mt++)
                #pragma unroll
                for (int nt = 0; nt < 4; nt++)
                    mma_tf32(acc[mt][nt], a[mt], bb[nt]);
        }
        __syncthreads();

        int k2 = (it + 2) << 5;
        if (k2 < K) issue_tile(it & 1, k2);
        asm volatile("cp.async.commit_group;" ::: "memory");
    }

    #pragma unroll
    for (int mt = 0; mt < 4; mt++) {
        #pragma unroll
        for (int nt = 0; nt < 4; nt++) {
            int n = n0 + wn0 + nt*8 + 2*t;
            if (PAD && n >= Nout) continue;
            #pragma unroll
            for (int half = 0; half < 2; half++) {
                int m = m0 + wm0 + mt*16 + g + half*8;
                float v0 = acc[mt][nt][half*2 + 0];
                float v1 = acc[mt][nt][half*2 + 1];
                if (bias) { v0 += bias[n]; v1 += bias[n+1]; }
                if (act)  { v0 *= normcdff(v0); v1 *= normcdff(v1); }
                if (res)  { v0 += res[(size_t)m*Nout + n];
                            v1 += res[(size_t)m*Nout + n + 1]; }
                if (RND)  { v0 = tf32r(v0); v1 = tf32r(v1); }
                *(float2*)(Y + (size_t)m*Nout + n) = make_float2(v0, v1);
            }
        }
    }
}

// ---------------------------------------------------------------------------
// Flash attention v2 (tf32 mma, online softmax in registers).
// ---------------------------------------------------------------------------
#define FQT  128
#define FKC  64
#define QSTR 36
#define VSTR 68
#define FSMEM ((FQT*QSTR + FKC*QSTR + 32*VSTR)*4)

__global__ __launch_bounds__(256) void flash_tc(
    const float* __restrict__ qkv, float* __restrict__ out)
{
    extern __shared__ float sm[];
    float* q_s = sm;                    // FQT x 36
    float* k_s = sm + FQT*QSTR;         // FKC x 36
    float* v_s = k_s + FKC*QSTR;        // 32 x 68 (transposed: [dh][key])

    int tid  = threadIdx.x;
    int warp = tid >> 5, lane = tid & 31;
    int g = lane >> 2, t = lane & 3;
    int b = blockIdx.z, h = blockIdx.y;
    int q0 = blockIdx.x * FQT;
    const float* qb = qkv + (size_t)b*N_*768 + h*32;
    const float scale = 0.17677669529663687f;   // 32^-0.5 (folded into Q)

    for (int ii = tid; ii < FQT*8; ii += 256) {
        int r = ii >> 3, c4q = (ii & 7) << 2;
        float4 v = *(const float4*)(qb + (size_t)(q0+r)*768 + c4q);
        q_s[r*QSTR + c4q + 0] = tf32r(v.x*scale);
        q_s[r*QSTR + c4q + 1] = tf32r(v.y*scale);
        q_s[r*QSTR + c4q + 2] = tf32r(v.z*scale);
        q_s[r*QSTR + c4q + 3] = tf32r(v.w*scale);
    }

    int row0 = warp * 16;
    float oa[4][4];
    #pragma unroll
    for (int nt = 0; nt < 4; nt++)
        #pragma unroll
        for (int c = 0; c < 4; c++) oa[nt][c] = 0.f;
    float mr0 = -1e30f, mr1 = -1e30f, lr0 = 0.f, lr1 = 0.f;

    int src_lo = (lane & ~3) | (t >> 1);
    int src_hi = src_lo | 2;

    int rA = tid >> 3, rB = rA + 32;
    int c4 = (tid & 7) << 2;

    float4 kfA = *(const float4*)(qb + (size_t)rA*768 + 256 + c4);
    float4 kfB = *(const float4*)(qb + (size_t)rB*768 + 256 + c4);
    float4 vfA = *(const float4*)(qb + (size_t)rA*768 + 512 + c4);
    float4 vfB = *(const float4*)(qb + (size_t)rB*768 + 512 + c4);

    for (int kt = 0; kt < N_; kt += FKC) {
        __syncthreads();
        k_s[rA*QSTR + c4 + 0] = tf32r(kfA.x);
        k_s[rA*QSTR + c4 + 1] = tf32r(kfA.y);
        k_s[rA*QSTR + c4 + 2] = tf32r(kfA.z);
        k_s[rA*QSTR + c4 + 3] = tf32r(kfA.w);
        k_s[rB*QSTR + c4 + 0] = tf32r(kfB.x);
        k_s[rB*QSTR + c4 + 1] = tf32r(kfB.y);
        k_s[rB*QSTR + c4 + 2] = tf32r(kfB.z);
        k_s[rB*QSTR + c4 + 3] = tf32r(kfB.w);
        v_s[(c4+0)*VSTR + rA] = tf32r(vfA.x);
        v_s[(c4+1)*VSTR + rA] = tf32r(vfA.y);
        v_s[(c4+2)*VSTR + rA] = tf32r(vfA.z);
        v_s[(c4+3)*VSTR + rA] = tf32r(vfA.w);
        v_s[(c4+0)*VSTR + rB] = tf32r(vfB.x);
        v_s[(c4+1)*VSTR + rB] = tf32r(vfB.y);
        v_s[(c4+2)*VSTR + rB] = tf32r(vfB.z);
        v_s[(c4+3)*VSTR + rB] = tf32r(vfB.w);
        __syncthreads();

        int ktn = kt + FKC;
        if (ktn < N_) {
            kfA = *(const float4*)(qb + (size_t)(ktn+rA)*768 + 256 + c4);
            kfB = *(const float4*)(qb + (size_t)(ktn+rB)*768 + 256 + c4);
            vfA = *(const float4*)(qb + (size_t)(ktn+rA)*768 + 512 + c4);
            vfB = *(const float4*)(qb + (size_t)(ktn+rB)*768 + 512 + c4);
        }

        float s[8][4];
        #pragma unroll
        for (int nt = 0; nt < 8; nt++)
            #pragma unroll
            for (int c = 0; c < 4; c++) s[nt][c] = 0.f;

        #pragma unroll
        for (int ks = 0; ks < 4; ks++) {
            int kc = ks*8 + t;
            u32 a[4];
            a[0] = __float_as_uint(q_s[(row0+g)*QSTR   + kc]);
            a[1] = __float_as_uint(q_s[(row0+8+g)*QSTR + kc]);
            a[2] = __float_as_uint(q_s[(row0+g)*QSTR   + kc + 4]);
            a[3] = __float_as_uint(q_s[(row0+8+g)*QSTR + kc + 4]);
            u32 bb[8][2];
            #pragma unroll
            for (int nt = 0; nt < 8; nt++) {
                int rr = nt*8 + g;
                bb[nt][0] = __float_as_uint(k_s[rr*QSTR + kc]);
                bb[nt][1] = __float_as_uint(k_s[rr*QSTR + kc + 4]);
            }
            #pragma unroll
            for (int nt = 0; nt < 8; nt++)
                mma_tf32(s[nt], a, bb[nt]);
        }

        {
            float m0 = -1e30f, m1 = -1e30f;
            #pragma unroll
            for (int nt = 0; nt < 8; nt++) {
                m0 = fmaxf(m0, fmaxf(s[nt][0], s[nt][1]));
                m1 = fmaxf(m1, fmaxf(s[nt][2], s[nt][3]));
            }
            #pragma unroll
            for (int o = 1; o <= 2; o <<= 1) {
                m0 = fmaxf(m0, __shfl_xor_sync(0xffffffffu, m0, o));
                m1 = fmaxf(m1, __shfl_xor_sync(0xffffffffu, m1, o));
            }
            float mn0 = fmaxf(mr0, m0);
            float mn1 = fmaxf(mr1, m1);
            float sf0 = __expf(mr0 - mn0);
            float sf1 = __expf(mr1 - mn1);
            mr0 = mn0; mr1 = mn1;
            float ls0 = 0.f, ls1 = 0.f;
            #pragma unroll
            for (int nt = 0; nt < 8; nt++) {
                float e0 = __expf(s[nt][0] - mn0);
                float e1 = __expf(s[nt][1] - mn0);
                float e2 = __expf(s[nt][2] - mn1);
                float e3 = __expf(s[nt][3] - mn1);
                ls0 += e0 + e1;  ls1 += e2 + e3;
                s[nt][0] = tf32r(e0);  s[nt][1] = tf32r(e1);
                s[nt][2] = tf32r(e2);  s[nt][3] = tf32r(e3);
            }
            #pragma unroll
            for (int o = 1; o <= 2; o <<= 1) {
                ls0 += __shfl_xor_sync(0xffffffffu, ls0, o);
                ls1 += __shfl_xor_sync(0xffffffffu, ls1, o);
            }
            lr0 = lr0*sf0 + ls0;
            lr1 = lr1*sf1 + ls1;
            #pragma unroll
            for (int nt = 0; nt < 4; nt++) {
                oa[nt][0] *= sf0;  oa[nt][1] *= sf0;
                oa[nt][2] *= sf1;  oa[nt][3] *= sf1;
            }
        }

        #pragma unroll
        for (int k8 = 0; k8 < 8; k8++) {
            float y00 = __shfl_sync(0xffffffffu, s[k8][0], src_lo);
            float y01 = __shfl_sync(0xffffffffu, s[k8][1], src_lo);
            float y10 = __shfl_sync(0xffffffffu, s[k8][0], src_hi);
            float y11 = __shfl_sync(0xffffffffu, s[k8][1], src_hi);
            float z00 = __shfl_sync(0xffffffffu, s[k8][2], src_lo);
            float z01 = __shfl_sync(0xffffffffu, s[k8][3], src_lo);
            float z10 = __shfl_sync(0xffffffffu, s[k8][2], src_hi);
            float z11 = __shfl_sync(0xffffffffu, s[k8][3], src_hi);
            u32 a[4];
            a[0] = __float_as_uint((t & 1) ? y01 : y00);
            a[2] = __float_as_uint((t & 1) ? y11 : y10);
            a[1] = __float_as_uint((t & 1) ? z01 : z00);
            a[3] = __float_as_uint((t & 1) ? z11 : z10);
            u32 bb[4][2];
            #pragma unroll
            for (int nt = 0; nt < 4; nt++) {
                int d = nt*8 + g;
                bb[nt][0] = __float_as_uint(v_s[d*VSTR + k8*8 + t]);
                bb[nt][1] = __float_as_uint(v_s[d*VSTR + k8*8 + t + 4]);
            }
            #pragma unroll
            for (int nt = 0; nt < 4; nt++)
                mma_tf32(oa[nt], a, bb[nt]);
        }
    }

    float i0 = 1.f / lr0;
    float i1 = 1.f / lr1;
    int r = q0 + row0 + g;
    #pragma unroll
    for (int nt = 0; nt < 4; nt++) {
        int col = h*32 + nt*8 + 2*t;
        *(float2*)(out + ((size_t)b*N_ + r)*C_ + col) =
            make_float2(tf32r(oa[nt][0]*i0), tf32r(oa[nt][1]*i0));
        *(float2*)(out + ((size_t)b*N_ + r + 8)*C_ + col) =
            make_float2(tf32r(oa[nt][2]*i1), tf32r(oa[nt][3]*i1));
    }
}

// ---------------------------------------------------------------------------
// Deformable gather: one warp per (b, n, head); lane = channel d.
// ---------------------------------------------------------------------------
__global__ __launch_bounds__(128) void deform_kernel(
    const float* __restrict__ ref, const float* __restrict__ off,
    const float* __restrict__ awl, const float* __restrict__ vp,
    float* __restrict__ out)
{
    int u = (blockIdx.x << 2) + (threadIdx.x >> 5);
    int lane = threadIdx.x & 31;
    int h  = u & 7;
    int bn = u >> 3;
    int b  = bn >> 10;

    float rx = ref[(size_t)bn*2 + 0]*32.f - 0.5f;
    float ry = ref[(size_t)bn*2 + 1]*32.f - 0.5f;
    const float* offp = off + (size_t)bn*64 + h*8;
    const float* awp  = awl + (size_t)bn*32 + h*4;

    float a0 = awp[0], a1 = awp[1], a2 = awp[2], a3 = awp[3];
    float mx = fmaxf(fmaxf(a0,a1), fmaxf(a2,a3));
    float e0 = __expf(a0-mx), e1 = __expf(a1-mx), e2 = __expf(a2-mx), e3 = __expf(a3-mx);
    float inv = 1.f/(e0+e1+e2+e3);
    float aw4[4] = {e0*inv, e1*inv, e2*inv, e3*inv};

    const float* vb = vp + (size_t)b*N_*C_ + h*32 + lane;
    float acc = 0.f;
    #pragma unroll
    for (int p = 0; p < 4; p++) {
        float gx = rx + offp[p*2+0];
        float gy = ry + offp[p*2+1];
        float x0f = floorf(gx), y0f = floorf(gy);
        float lx = gx - x0f, ly = gy - y0f;
        int x0 = (int)x0f, y0 = (int)y0f;
        float s = 0.f;
        #pragma unroll
        for (int cy = 0; cy < 2; cy++) {
            int yi = y0 + cy;
            float wy = cy ? ly : (1.f - ly);
            bool vy = (yi >= 0) && (yi < 32);
            int yc = min(max(yi, 0), 31);
            #pragma unroll
            for (int cx = 0; cx < 2; cx++) {
                int xi = x0 + cx;
                float wx = cx ? lx : (1.f - lx);
                bool vx = (xi >= 0) && (xi < 32);
                int xc = min(max(xi, 0), 31);
                float val = (vx && vy) ? vb[(size_t)(yc*32 + xc)*C_] : 0.f;
                s = fmaf(val, wx*wy, s);
            }
        }
        acc = fmaf(aw4[p], s, acc);
    }
    out[(size_t)bn*C_ + h*32 + lane] = tf32r(acc);
}

// ---------------------------------------------------------------------------
// Launch
// ---------------------------------------------------------------------------
extern "C" void kernel_launch(void* const* d_in, const int* in_sizes, int n_in,
                              void* d_out, int out_size)
{
    const float* x       = (const float*)d_in[0];
    const float* ref     = (const float*)d_in[1];
    const float* value   = (const float*)d_in[2];
    const float* ln1w    = (const float*)d_in[3];
    const float* ln1b    = (const float*)d_in[4];
    const float* ln2w    = (const float*)d_in[5];
    const float* ln2b    = (const float*)d_in[6];
    const float* ln3w    = (const float*)d_in[7];
    const float* ln3b    = (const float*)d_in[8];
    const float* qkv_w   = (const float*)d_in[9];
    const float* proj_w  = (const float*)d_in[10];
    const float* proj_b  = (const float*)d_in[11];
    const float* off_w   = (const float*)d_in[12];
    const float* off_b   = (const float*)d_in[13];
    const float* aw_w    = (const float*)d_in[14];
    const float* aw_b    = (const float*)d_in[15];
    const float* vproj_w = (const float*)d_in[16];
    const float* vproj_b = (const float*)d_in[17];
    const float* oproj_w = (const float*)d_in[18];
    const float* oproj_b = (const float*)d_in[19];
    const float* fc1_w   = (const float*)d_in[20];
    const float* fc1_b   = (const float*)d_in[21];
    const float* fc2_w   = (const float*)d_in[22];
    const float* fc2_b   = (const float*)d_in[23];
    float* out = (float*)d_out;

    float *y, *qkvb, *tmp, *x2, *offb, *awb, *vpb, *h1, *wbuf, *valb;
    cudaGetSymbolAddress((void**)&y,    g_y);
    cudaGetSymbolAddress((void**)&qkvb, g_qkv);
    cudaGetSymbolAddress((void**)&tmp,  g_tmp);
    cudaGetSymbolAddress((void**)&x2,   g_x2);
    cudaGetSymbolAddress((void**)&offb, g_off);
    cudaGetSymbolAddress((void**)&awb,  g_awl);
    cudaGetSymbolAddress((void**)&vpb,  g_vp);
    cudaGetSymbolAddress((void**)&h1,   g_h1);
    cudaGetSymbolAddress((void**)&wbuf, g_w);
    cudaGetSymbolAddress((void**)&valb, g_val);

    cudaFuncSetAttribute(flash_tc,
        cudaFuncAttributeMaxDynamicSharedMemorySize, FSMEM);
    cudaFuncSetAttribute(gemm_tc_t<0,0>,
        cudaFuncAttributeMaxDynamicSharedMemorySize, GSMEM);
    cudaFuncSetAttribute(gemm_tc_t<1,0>,
        cudaFuncAttributeMaxDynamicSharedMemorySize, GSMEM);
    cudaFuncSetAttribute(gemm_tc_t<0,1>,
        cudaFuncAttributeMaxDynamicSharedMemorySize, GSMEM);

    const float* wq  = wbuf + WOFF_QKV;
    const float* wp  = wbuf + WOFF_PROJ;
    const float* wo  = wbuf + WOFF_OFF;
    const float* wa  = wbuf + WOFF_AW;
    const float* wv  = wbuf + WOFF_VPROJ;
    const float* wop = wbuf + WOFF_OPROJ;
    const float* w1  = wbuf + WOFF_FC1;
    const float* w2  = wbuf + WOFF_FC2;

    // pre-round weights + value (rna tf32)
    round_weights<<<(WTOT/4 + 255)/256, 256>>>(qkv_w, proj_w, off_w, aw_w,
        vproj_w, oproj_w, fc1_w, fc2_w, wbuf);
    round_buf<<<(M_*C_/4 + 255)/256, 256>>>(value, valb, M_*C_/4);

    // x1 = x + attn(ln1(x))
    ln_kernel<<<M_, 256>>>(x, ln1w, ln1b, y);
    gemm_tc_t<0,0><<<dim3(6,128), 256, GSMEM>>>(y, wq, nullptr, nullptr, qkvb, M_, 768, 256, 0);
    flash_tc<<<dim3(N_/FQT, NH_, B_), 256, FSMEM>>>(qkvb, tmp);
    gemm_tc_t<0,0><<<dim3(2,128), 256, GSMEM>>>(tmp, wp, proj_b, x, x2, M_, 256, 256, 0);

    // x2 = x1 + deform(ln2(x1))
    ln_kernel<<<M_, 256>>>(x2, ln2w, ln2b, y);
    gemm_tc_t<1,0><<<dim3(1,128), 256, GSMEM>>>(y, wo, off_b, nullptr, offb, M_, 64, 256, 0);
    gemm_tc_t<1,0><<<dim3(1,128), 256, GSMEM>>>(y, wa, aw_b, nullptr, awb, M_, 32, 256, 0);
    gemm_tc_t<0,0><<<dim3(2,128), 256, GSMEM>>>(valb, wv, vproj_b, nullptr, vpb, M_, 256, 256, 0);
    deform_kernel<<<32768, 128>>>(ref, offb, awb, vpb, tmp);
    gemm_tc_t<0,0><<<dim3(2,128), 256, GSMEM>>>(tmp, wop, oproj_b, x2, x2, M_, 256, 256, 0);

    // out = x2 + fc2(gelu(fc1(ln3(x2))))
    ln_kernel<<<M_, 256>>>(x2, ln3w, ln3b, y);
    gemm_tc_t<0,1><<<dim3(8,128), 256, GSMEM>>>(y, w1, fc1_b, nullptr, h1, M_, 1024, 256, 1);
    gemm_tc_t<0,0><<<dim3(2,128), 256, GSMEM>>>(h1, w2, fc2_b, x2, out, M_, 256, 1024, 0);
}